// round 1
// baseline (speedup 1.0000x reference)
#include <cuda_runtime.h>
#include <math.h>
#include <stdint.h>

// Problem dims
#define BQ 8
#define NOBJ 128
#define NATT 4
#define TT 12
#define MC 2048
#define ED 128
#define IDD 64
#define AD 64
#define HD 256
#define CC (MC + NOBJ)   // 2176
#define NCHUNK 17        // CC / 128

// ---------------- scratch (device globals; no allocs allowed) ----------------
__device__ float g_obj_in [BQ][NOBJ][ED];
__device__ float g_obj_out[BQ][NOBJ][ED];
__device__ float g_obj_id [BQ][NOBJ][IDD];
__device__ float g_att   [BQ][CC][AD];     // current attention state
__device__ float g_amean [BQ][CC];         // mean over AD of g_att
__device__ float g_meta  [TT][BQ][AD];     // meta after update at step t
__device__ float g_arg   [TT][BQ][ED];     // gathered arguments
__device__ float g_Mpart [BQ][NCHUNK][ED*ED];
__device__ float g_M     [BQ][ED*ED];      // [e][d]
__device__ float g_G     [BQ][CC][ED];     // gathered

// ---------------- row accessors (concept part shared across batch) ----------
__device__ __forceinline__ const float* axon_row(const float* conc_out, int b, int c) {
    return (c < MC) ? (conc_out + (size_t)c * ED) : &g_obj_out[b][c - MC][0];
}
__device__ __forceinline__ const float* dend_row(const float* conc_in, int b, int c) {
    return (c < MC) ? (conc_in + (size_t)c * ED) : &g_obj_in[b][c - MC][0];
}
__device__ __forceinline__ const float* id_row(const float* conc_id, int b, int c) {
    return (c < MC) ? (conc_id + (size_t)c * IDD) : &g_obj_id[b][c - MC][0];
}

// ---------------- init kernels ----------------------------------------------
// one block per (b, n); thread d sums the 4 attribute embeddings
__global__ void k_objects(const int* __restrict__ scene,
                          const float* __restrict__ a_in,
                          const float* __restrict__ a_out,
                          const float* __restrict__ a_id) {
    int bn = blockIdx.x;
    int b = bn / NOBJ, n = bn % NOBJ;
    int d = threadIdx.x;
    const int* sc = scene + (b * NOBJ + n) * NATT;
    float si = 0.f, so = 0.f, sid = 0.f;
#pragma unroll
    for (int a = 0; a < NATT; a++) {
        int s = sc[a];
        float m = (s != -1) ? 1.f : 0.f;
        int idx = s + 1;
        si += m * a_in[(size_t)idx * ED + d];
        so += m * a_out[(size_t)idx * ED + d];
        if (d < IDD) sid += m * a_id[(size_t)idx * IDD + d];
    }
    g_obj_in[b][n][d] = si;
    g_obj_out[b][n][d] = so;
    if (d < IDD) g_obj_id[b][n][d] = sid;
}

// g_arg[t][b] = concept_emb_out[program_arg[b][t]]
__global__ void k_args(const int* __restrict__ prog_arg,
                       const float* __restrict__ conc_out) {
    int tb = blockIdx.x;
    int t = tb / BQ, b = tb % BQ;
    int arg = prog_arg[b * TT + t];
    g_arg[t][b][threadIdx.x] = conc_out[(size_t)arg * ED + threadIdx.x];
}

// attention state init + initial a_mean; one thread per (b,c)
__global__ void k_att_init(const float* __restrict__ att_init) {
    int i = blockIdx.x * blockDim.x + threadIdx.x;
    if (i >= BQ * CC) return;
    int b = i / CC, c = i % CC;
    float s = 0.f;
#pragma unroll
    for (int a = 0; a < AD; a++) {
        float v = att_init[a];
        g_att[b][c][a] = v;
        s += v;
    }
    g_amean[b][c] = s * (1.f / AD);
}

// meta recurrence is attention-independent -> precompute all T steps.
// one block per batch, 256 threads
__global__ void k_meta(const int* __restrict__ prog_op,
                       const float* __restrict__ w1, const float* __restrict__ b1,
                       const float* __restrict__ w2, const float* __restrict__ b2,
                       const float* __restrict__ att_init) {
    __shared__ float meta_s[AD];
    __shared__ float hid_s[HD];
    int b = blockIdx.x, tid = threadIdx.x;
    if (tid < AD) meta_s[tid] = att_init[tid];   // meta0 = attention_init
    __syncthreads();
    for (int t = 0; t < TT; t++) {
        // hidden = relu([meta, arg] @ w1.T + b1); w1 rows are length 192
        const float* w1r = w1 + (size_t)tid * (AD + ED);
        float acc = b1[tid];
#pragma unroll
        for (int k = 0; k < AD; k++) acc += meta_s[k] * w1r[k];
        const float* argp = &g_arg[t][b][0];
#pragma unroll
        for (int k = 0; k < ED; k++) acc += argp[k] * w1r[AD + k];
        hid_s[tid] = fmaxf(acc, 0.f);
        __syncthreads();
        float m = (prog_op[b * TT + t] == 0) ? 1.f : 0.f;
        float nm = 0.f;
        if (tid < AD) {
            const float* w2r = w2 + (size_t)tid * HD;
            float a2 = b2[tid];
#pragma unroll
            for (int k = 0; k < HD; k++) a2 += hid_s[k] * w2r[k];
            nm = m * a2 + (1.f - m) * meta_s[tid];
        }
        __syncthreads();
        if (tid < AD) {
            meta_s[tid] = nm;
            g_meta[t][b][tid] = nm;
        }
        __syncthreads();
    }
}

// proj[t,b,c] = arg . axon / ED ; ins_hist[t,b,c,a] = meta[t,b,a]*proj
// grid (CC/128, BQ, TT), 128 threads
__global__ void k_proj_ins(const float* __restrict__ conc_out,
                           float* __restrict__ ins_hist) {
    __shared__ float arg_s[ED];
    __shared__ float meta_s[AD];
    __shared__ float proj_s[128];
    int t = blockIdx.z, b = blockIdx.y, c0 = blockIdx.x * 128;
    int tid = threadIdx.x;
    arg_s[tid] = g_arg[t][b][tid];
    if (tid < AD) meta_s[tid] = g_meta[t][b][tid];
    __syncthreads();
    int c = c0 + tid;
    const float* ax = axon_row(conc_out, b, c);
    float acc = 0.f;
#pragma unroll 8
    for (int e = 0; e < ED; e++) acc += arg_s[e] * ax[e];
    proj_s[tid] = acc * (1.f / ED);
    __syncthreads();
    float* outp = ins_hist + (((size_t)t * BQ + b) * CC + c0) * AD;
    for (int i = tid; i < 128 * AD; i += 128) {
        int cl = i >> 6, a = i & 63;
        outp[i] = proj_s[cl] * meta_s[a];
    }
}

// ---------------- per-step kernels -------------------------------------------
// M partials: block (chunk, b) reduces 128 c's into a 128x128 outer-product sum
__global__ void k_M(const float* __restrict__ conc_out,
                    const float* __restrict__ conc_id) {
    int b = blockIdx.y, ch = blockIdx.x;
    int c0 = ch * 128;
    int tid = threadIdx.x;
    int ty = tid >> 4, tx = tid & 15;
    __shared__ __align__(16) float sax[8][ED];
    __shared__ __align__(16) float sia[8][ED];
    float acc[8][8];
#pragma unroll
    for (int i = 0; i < 8; i++)
#pragma unroll
        for (int j = 0; j < 8; j++) acc[i][j] = 0.f;

    for (int g = 0; g < 16; g++) {
        int cb = c0 + g * 8;
        if (tid < 128) {
#pragma unroll
            for (int r = 0; r < 8; r++) {
                int c = cb + r;
                sax[r][tid] = axon_row(conc_out, b, c)[tid] * g_amean[b][c];
            }
        } else {
            int d = tid - 128;
#pragma unroll
            for (int r = 0; r < 8; r++) {
                int c = cb + r;
                sia[r][d] = (d < IDD) ? id_row(conc_id, b, c)[d]
                                      : g_att[b][c][d - IDD];
            }
        }
        __syncthreads();
#pragma unroll
        for (int r = 0; r < 8; r++) {
            float4 a0 = *reinterpret_cast<const float4*>(&sax[r][ty * 8]);
            float4 a1 = *reinterpret_cast<const float4*>(&sax[r][ty * 8 + 4]);
            float4 b0 = *reinterpret_cast<const float4*>(&sia[r][tx * 8]);
            float4 b1 = *reinterpret_cast<const float4*>(&sia[r][tx * 8 + 4]);
            float av[8] = {a0.x, a0.y, a0.z, a0.w, a1.x, a1.y, a1.z, a1.w};
            float bv[8] = {b0.x, b0.y, b0.z, b0.w, b1.x, b1.y, b1.z, b1.w};
#pragma unroll
            for (int i = 0; i < 8; i++)
#pragma unroll
                for (int j = 0; j < 8; j++) acc[i][j] += av[i] * bv[j];
        }
        __syncthreads();
    }
    float* outp = g_Mpart[b][ch];
#pragma unroll
    for (int i = 0; i < 8; i++)
#pragma unroll
        for (int j = 0; j < 8; j++)
            outp[(ty * 8 + i) * ED + tx * 8 + j] = acc[i][j];
}

// deterministic reduce of the 17 chunk partials
__global__ void k_Mred() {
    int i = blockIdx.x * blockDim.x + threadIdx.x;  // < BQ*ED*ED = 131072
    int b = i >> 14;
    int ed = i & 16383;
    float s = 0.f;
#pragma unroll
    for (int k = 0; k < NCHUNK; k++) s += g_Mpart[b][k][ed];
    g_M[b][ed] = s;
}

// gathered = dendron @ M / C ; block handles 32 c rows; thread owns column d
__global__ void k_G(const float* __restrict__ conc_in) {
    __shared__ float den_s[32][ED];
    int b = blockIdx.y, c0 = blockIdx.x * 32;
    int tid = threadIdx.x;  // 128 threads; d = tid
#pragma unroll
    for (int k = 0; k < 32; k++)
        den_s[k][tid] = dend_row(conc_in, b, c0 + k)[tid];
    __syncthreads();
    float acc[32];
#pragma unroll
    for (int i = 0; i < 32; i++) acc[i] = 0.f;
    const float* Mrow = g_M[b];
#pragma unroll 4
    for (int e = 0; e < ED; e++) {
        float m = Mrow[e * ED + tid];
#pragma unroll
        for (int i = 0; i < 32; i++) acc[i] += den_s[i][e] * m;
    }
#pragma unroll
    for (int i = 0; i < 32; i++)
        g_G[b][c0 + i][tid] = acc[i] * (1.f / CC);
}

// axon MLP + attention update + history writes + next-step a_mean
// block: 16 c rows, 256 threads. grid (CC/16, BQ)
__global__ void k_mlp_update(int t,
                             const int* __restrict__ prog_op,
                             const float* __restrict__ w1, const float* __restrict__ b1,
                             const float* __restrict__ w2, const float* __restrict__ b2,
                             const float* __restrict__ ins_hist,
                             float* __restrict__ att_hist,
                             float* __restrict__ trans_hist) {
    __shared__ float Gt[16][ED];   // gathered tile
    __shared__ float Ht[16][HD];   // hidden tile
    __shared__ float At[16][AD];   // new attention tile (for mean)
    int b = blockIdx.y, c0 = blockIdx.x * 16;
    int tid = threadIdx.x;

    // load gathered tile (coalesced)
#pragma unroll
    for (int k = 0; k < 8; k++) {
        int v = k * 256 + tid;
        int row = v >> 7, e = v & 127;
        Gt[row][e] = g_G[b][c0 + row][e];
    }
    __syncthreads();

    // hidden: thread tid = hidden unit h, all 16 rows
    {
        int h = tid;
        const float* w1r = w1 + (size_t)h * ED;
        float acc[16];
        float bb = b1[h];
#pragma unroll
        for (int i = 0; i < 16; i++) acc[i] = bb;
#pragma unroll 4
        for (int e = 0; e < ED; e++) {
            float w = w1r[e];
#pragma unroll
            for (int i = 0; i < 16; i++) acc[i] += Gt[i][e] * w;
        }
#pragma unroll
        for (int i = 0; i < 16; i++) Ht[i][h] = fmaxf(acc[i], 0.f);
    }
    __syncthreads();

    int op = prog_op[b * TT + t];
    float insg = (op == 1) ? 1.f : 0.f;
    float trg  = (op == 2) ? 1.f : 0.f;

    // output layer + skip + state update; thread = (c group, j)
    int j = tid & 63;
    int cg = tid >> 6;  // 0..3
    const float* w2r = w2 + (size_t)j * HD;
    float bj = b2[j];
#pragma unroll
    for (int cl = 0; cl < 4; cl++) {
        int c_local = cl * 4 + cg;
        float tr = bj;
#pragma unroll 4
        for (int h = 0; h < HD; h++) tr += Ht[c_local][h] * w2r[h];
        tr += Gt[c_local][IDD + j];  // skip connection
        int c = c0 + c_local;
        size_t hidx = (((size_t)t * BQ + b) * CC + c) * AD + j;
        float ins_v = ins_hist[hidx];
        float v = g_att[b][c][j] + insg * ins_v + trg * tr;
        v = (v >= 0.f) ? v : 0.01f * v;
        v = fminf(fmaxf(v, -1.f), 2.f);
        g_att[b][c][j] = v;
        att_hist[hidx] = v;
        trans_hist[hidx] = tr;
        At[c_local][j] = v;
    }
    __syncthreads();
    if (tid < 16) {
        float s = 0.f;
#pragma unroll
        for (int a = 0; a < AD; a++) s += At[tid][a];
        g_amean[b][c0 + tid] = s * (1.f / AD);
    }
}

// log_softmax over C of final a_mean; one block per batch
__global__ void k_softmax(float* __restrict__ out) {
    __shared__ float red[256];
    int b = blockIdx.x, tid = threadIdx.x;
    float mx = -1e30f;
    for (int c = tid; c < CC; c += 256) mx = fmaxf(mx, g_amean[b][c]);
    red[tid] = mx;
    __syncthreads();
    for (int s = 128; s > 0; s >>= 1) {
        if (tid < s) red[tid] = fmaxf(red[tid], red[tid + s]);
        __syncthreads();
    }
    mx = red[0];
    __syncthreads();
    float sum = 0.f;
    for (int c = tid; c < CC; c += 256) sum += expf(g_amean[b][c] - mx);
    red[tid] = sum;
    __syncthreads();
    for (int s = 128; s > 0; s >>= 1) {
        if (tid < s) red[tid] += red[tid + s];
        __syncthreads();
    }
    float lse = mx + logf(red[0]);
    for (int c = tid; c < CC; c += 256) out[(size_t)b * CC + c] = g_amean[b][c] - lse;
}

// ---------------- launch ------------------------------------------------------
extern "C" void kernel_launch(void* const* d_in, const int* in_sizes, int n_in,
                              void* d_out, int out_size) {
    const int*   scene    = (const int*)d_in[0];
    const int*   prog_op  = (const int*)d_in[1];
    const int*   prog_arg = (const int*)d_in[2];
    const float* attr_in  = (const float*)d_in[3];
    const float* attr_out = (const float*)d_in[4];
    const float* attr_id  = (const float*)d_in[5];
    const float* conc_in  = (const float*)d_in[6];
    const float* conc_out = (const float*)d_in[7];
    const float* conc_id  = (const float*)d_in[8];
    // d_in[9] embed_init, d_in[10] identity_init: unused by the reference
    const float* att_init = (const float*)d_in[11];
    const float* axon_w1  = (const float*)d_in[12];
    const float* axon_b1  = (const float*)d_in[13];
    const float* axon_w2  = (const float*)d_in[14];
    const float* axon_b2  = (const float*)d_in[15];
    const float* meta_w1  = (const float*)d_in[16];
    const float* meta_b1  = (const float*)d_in[17];
    const float* meta_w2  = (const float*)d_in[18];
    const float* meta_b2  = (const float*)d_in[19];

    float* out        = (float*)d_out;
    float* att_hist   = out + (size_t)BQ * CC;
    float* ins_hist   = att_hist + (size_t)TT * BQ * CC * AD;
    float* trans_hist = ins_hist + (size_t)TT * BQ * CC * AD;

    k_objects<<<BQ * NOBJ, 128>>>(scene, attr_in, attr_out, attr_id);
    k_args<<<TT * BQ, 128>>>(prog_arg, conc_out);
    k_att_init<<<(BQ * CC + 127) / 128, 128>>>(att_init);
    k_meta<<<BQ, 256>>>(prog_op, meta_w1, meta_b1, meta_w2, meta_b2, att_init);
    k_proj_ins<<<dim3(NCHUNK, BQ, TT), 128>>>(conc_out, ins_hist);

    for (int t = 0; t < TT; t++) {
        k_M<<<dim3(NCHUNK, BQ), 256>>>(conc_out, conc_id);
        k_Mred<<<(BQ * ED * ED) / 256, 256>>>();
        k_G<<<dim3(CC / 32, BQ), 128>>>(conc_in);
        k_mlp_update<<<dim3(CC / 16, BQ), 256>>>(t, prog_op,
                                                 axon_w1, axon_b1, axon_w2, axon_b2,
                                                 ins_hist, att_hist, trans_hist);
    }
    k_softmax<<<BQ, 256>>>(out);
}

// round 3
// speedup vs baseline: 8.0731x; 8.0731x over previous
#include <cuda_runtime.h>
#include <math.h>
#include <stdint.h>

// Problem dims
#define BQ 8
#define NOBJ 128
#define NATT 4
#define TT 12
#define MC 2048
#define ED 128
#define IDD 64
#define AD 64
#define HD 256
#define CC (MC + NOBJ)   // 2176
#define NCHUNK 17        // CC / 128

// ---------------- scratch (device globals; no allocs allowed) ----------------
__device__ float g_obj_in [BQ][NOBJ][ED];
__device__ float g_obj_out[BQ][NOBJ][ED];
__device__ float g_obj_id [BQ][NOBJ][IDD];
__device__ float g_att   [BQ][CC][AD];     // current attention state
__device__ float g_amean [BQ][CC];         // mean over AD of g_att
__device__ float g_meta  [TT][BQ][AD];     // meta after update at step t
__device__ float g_arg   [TT][BQ][ED];     // gathered arguments
__device__ float g_Mpart [BQ][NCHUNK][ED*ED];
__device__ float g_M     [BQ][ED*ED];      // [e][d]
__device__ float g_G     [BQ][CC][ED];     // gathered

// ---------------- row accessors (concept part shared across batch) ----------
__device__ __forceinline__ const float* axon_row(const float* conc_out, int b, int c) {
    return (c < MC) ? (conc_out + (size_t)c * ED) : &g_obj_out[b][c - MC][0];
}
__device__ __forceinline__ const float* dend_row(const float* conc_in, int b, int c) {
    return (c < MC) ? (conc_in + (size_t)c * ED) : &g_obj_in[b][c - MC][0];
}
__device__ __forceinline__ const float* id_row(const float* conc_id, int b, int c) {
    return (c < MC) ? (conc_id + (size_t)c * IDD) : &g_obj_id[b][c - MC][0];
}

// ---------------- init kernels ----------------------------------------------
// one block per (b, n); thread d sums the 4 attribute embeddings
__global__ void k_objects(const int* __restrict__ scene,
                          const float* __restrict__ a_in,
                          const float* __restrict__ a_out,
                          const float* __restrict__ a_id) {
    int bn = blockIdx.x;
    int b = bn / NOBJ, n = bn % NOBJ;
    int d = threadIdx.x;
    const int* sc = scene + (b * NOBJ + n) * NATT;
    float si = 0.f, so = 0.f, sid = 0.f;
#pragma unroll
    for (int a = 0; a < NATT; a++) {
        int s = sc[a];
        float m = (s != -1) ? 1.f : 0.f;
        int idx = s + 1;
        si += m * a_in[(size_t)idx * ED + d];
        so += m * a_out[(size_t)idx * ED + d];
        if (d < IDD) sid += m * a_id[(size_t)idx * IDD + d];
    }
    g_obj_in[b][n][d] = si;
    g_obj_out[b][n][d] = so;
    if (d < IDD) g_obj_id[b][n][d] = sid;
}

// g_arg[t][b] = concept_emb_out[program_arg[b][t]]
__global__ void k_args(const int* __restrict__ prog_arg,
                       const float* __restrict__ conc_out) {
    int tb = blockIdx.x;
    int t = tb / BQ, b = tb % BQ;
    int arg = prog_arg[b * TT + t];
    g_arg[t][b][threadIdx.x] = conc_out[(size_t)arg * ED + threadIdx.x];
}

// attention state init: fully coalesced element-parallel fill
__global__ void k_att_init(const float* __restrict__ att_init) {
    int i = blockIdx.x * blockDim.x + threadIdx.x;
    if (i >= BQ * CC * AD) return;
    ((float*)g_att)[i] = att_init[i & (AD - 1)];
}

// initial a_mean: constant = mean(att_init), one value per (b,c)
__global__ void k_amean_init(const float* __restrict__ att_init) {
    int i = blockIdx.x * blockDim.x + threadIdx.x;
    if (i >= BQ * CC) return;
    float s = 0.f;
#pragma unroll
    for (int a = 0; a < AD; a++) s += att_init[a];
    ((float*)g_amean)[i] = s * (1.f / AD);
}

// meta recurrence: warp-cooperative dots, coalesced weight reads.
// one block per batch (grid=8), 256 threads = 8 warps
__global__ void k_meta(const int* __restrict__ prog_op,
                       const float* __restrict__ w1, const float* __restrict__ b1,
                       const float* __restrict__ w2, const float* __restrict__ b2,
                       const float* __restrict__ att_init) {
    __shared__ float x[AD + ED];   // meta(64) || arg(128)
    __shared__ float hid[HD];
    __shared__ float nm[AD];
    int b = blockIdx.x, tid = threadIdx.x;
    int warp = tid >> 5, lane = tid & 31;
    if (tid < AD) x[tid] = att_init[tid];
    for (int t = 0; t < TT; t++) {
        if (tid < ED) x[AD + tid] = g_arg[t][b][tid];
        __syncthreads();
        // layer 1: warp w -> hidden units [w*32, w*32+32)
        for (int hh = 0; hh < 32; hh++) {
            int h = warp * 32 + hh;
            const float* wr = w1 + (size_t)h * (AD + ED);
            float p = 0.f;
#pragma unroll
            for (int m = 0; m < 6; m++) p += x[lane + 32 * m] * wr[lane + 32 * m];
#pragma unroll
            for (int o = 16; o; o >>= 1) p += __shfl_xor_sync(0xffffffffu, p, o);
            if (lane == 0) hid[h] = fmaxf(p + b1[h], 0.f);
        }
        __syncthreads();
        float mg = (prog_op[b * TT + t] == 0) ? 1.f : 0.f;
        // layer 2: warp w -> outputs [w*8, w*8+8)
        for (int jj = 0; jj < 8; jj++) {
            int j = warp * 8 + jj;
            const float* wr = w2 + (size_t)j * HD;
            float p = 0.f;
#pragma unroll
            for (int m = 0; m < 8; m++) p += hid[lane + 32 * m] * wr[lane + 32 * m];
#pragma unroll
            for (int o = 16; o; o >>= 1) p += __shfl_xor_sync(0xffffffffu, p, o);
            if (lane == 0) nm[j] = mg * (p + b2[j]) + (1.f - mg) * x[j];
        }
        __syncthreads();
        if (tid < AD) {
            x[tid] = nm[tid];
            g_meta[t][b][tid] = nm[tid];
        }
        __syncthreads();
    }
}

// proj + ins_hist: warp-cooperative dots (coalesced axon reads)
// grid (CC/16, BQ, TT), 256 threads; 16 c rows per block
__global__ void k_proj_ins(const float* __restrict__ conc_out,
                           float* __restrict__ ins_hist) {
    __shared__ float arg_s[ED];
    __shared__ float meta_s[AD];
    __shared__ float proj_s[16];
    int t = blockIdx.z, b = blockIdx.y, c0 = blockIdx.x * 16;
    int tid = threadIdx.x;
    if (tid < ED) arg_s[tid] = g_arg[t][b][tid];
    else if (tid < ED + AD) meta_s[tid - ED] = g_meta[t][b][tid - ED];
    __syncthreads();
    int warp = tid >> 5, lane = tid & 31;
#pragma unroll
    for (int r = 0; r < 2; r++) {
        int cl = warp * 2 + r;
        const float* ax = axon_row(conc_out, b, c0 + cl);
        float p = 0.f;
#pragma unroll
        for (int m = 0; m < 4; m++) p += arg_s[lane + 32 * m] * ax[lane + 32 * m];
#pragma unroll
        for (int o = 16; o; o >>= 1) p += __shfl_xor_sync(0xffffffffu, p, o);
        if (lane == 0) proj_s[cl] = p * (1.f / ED);
    }
    __syncthreads();
    float* outp = ins_hist + (((size_t)t * BQ + b) * CC + c0) * AD;
#pragma unroll
    for (int k = 0; k < 4; k++) {
        int i = k * 256 + tid;
        outp[i] = proj_s[i >> 6] * meta_s[i & 63];
    }
}

// ---------------- per-step kernels -------------------------------------------
// M partials: block (chunk, b) reduces 128 c's into a 128x128 outer-product sum
__global__ void k_M(const float* __restrict__ conc_out,
                    const float* __restrict__ conc_id) {
    int b = blockIdx.y, ch = blockIdx.x;
    int c0 = ch * 128;
    int tid = threadIdx.x;
    int ty = tid >> 4, tx = tid & 15;
    __shared__ __align__(16) float sax[8][ED];
    __shared__ __align__(16) float sia[8][ED];
    float acc[8][8];
#pragma unroll
    for (int i = 0; i < 8; i++)
#pragma unroll
        for (int j = 0; j < 8; j++) acc[i][j] = 0.f;

    for (int g = 0; g < 16; g++) {
        int cb = c0 + g * 8;
        if (tid < 128) {
#pragma unroll
            for (int r = 0; r < 8; r++) {
                int c = cb + r;
                sax[r][tid] = axon_row(conc_out, b, c)[tid] * g_amean[b][c];
            }
        } else {
            int d = tid - 128;
#pragma unroll
            for (int r = 0; r < 8; r++) {
                int c = cb + r;
                sia[r][d] = (d < IDD) ? id_row(conc_id, b, c)[d]
                                      : g_att[b][c][d - IDD];
            }
        }
        __syncthreads();
#pragma unroll
        for (int r = 0; r < 8; r++) {
            float4 a0 = *reinterpret_cast<const float4*>(&sax[r][ty * 8]);
            float4 a1 = *reinterpret_cast<const float4*>(&sax[r][ty * 8 + 4]);
            float4 b0 = *reinterpret_cast<const float4*>(&sia[r][tx * 8]);
            float4 b1 = *reinterpret_cast<const float4*>(&sia[r][tx * 8 + 4]);
            float av[8] = {a0.x, a0.y, a0.z, a0.w, a1.x, a1.y, a1.z, a1.w};
            float bv[8] = {b0.x, b0.y, b0.z, b0.w, b1.x, b1.y, b1.z, b1.w};
#pragma unroll
            for (int i = 0; i < 8; i++)
#pragma unroll
                for (int j = 0; j < 8; j++) acc[i][j] += av[i] * bv[j];
        }
        __syncthreads();
    }
    float* outp = g_Mpart[b][ch];
#pragma unroll
    for (int i = 0; i < 8; i++)
#pragma unroll
        for (int j = 0; j < 8; j++)
            outp[(ty * 8 + i) * ED + tx * 8 + j] = acc[i][j];
}

// deterministic reduce of the 17 chunk partials
__global__ void k_Mred() {
    int i = blockIdx.x * blockDim.x + threadIdx.x;  // < BQ*ED*ED = 131072
    int b = i >> 14;
    int ed = i & 16383;
    float s = 0.f;
#pragma unroll
    for (int k = 0; k < NCHUNK; k++) s += g_Mpart[b][k][ed];
    g_M[b][ed] = s;
}

// gathered = dendron @ M / C
// block: 64 c rows x 128 d cols, 256 threads; register tile 8 rows x 4 d
__global__ void __launch_bounds__(256) k_G(const float* __restrict__ conc_in) {
    __shared__ float den[64][128];
    __shared__ float Ms[32][128];
    int b = blockIdx.y, c0 = blockIdx.x * 64;
    int tid = threadIdx.x;
    int tx = tid & 31, ty = tid >> 5;
#pragma unroll 4
    for (int k = 0; k < 32; k++) {
        int lin = k * 256 + tid;
        int r = lin >> 7, e = lin & 127;
        den[r][e] = dend_row(conc_in, b, c0 + r)[e];
    }
    float acc[8][4];
#pragma unroll
    for (int r = 0; r < 8; r++)
#pragma unroll
        for (int i = 0; i < 4; i++) acc[r][i] = 0.f;
    const float* Mb = g_M[b];
    for (int e0 = 0; e0 < 128; e0 += 32) {
        __syncthreads();
#pragma unroll 4
        for (int k = 0; k < 16; k++) {
            int lin = k * 256 + tid;
            int er = lin >> 7, d = lin & 127;
            Ms[er][d] = Mb[(e0 + er) * 128 + d];
        }
        __syncthreads();
#pragma unroll 2
        for (int e = 0; e < 32; e++) {
            float4 mv = *reinterpret_cast<const float4*>(&Ms[e][tx * 4]);
#pragma unroll
            for (int r = 0; r < 8; r++) {
                float dv = den[ty * 8 + r][e0 + e];
                acc[r][0] += dv * mv.x;
                acc[r][1] += dv * mv.y;
                acc[r][2] += dv * mv.z;
                acc[r][3] += dv * mv.w;
            }
        }
    }
    const float inv = 1.f / CC;
#pragma unroll
    for (int r = 0; r < 8; r++) {
        float4 v = make_float4(acc[r][0] * inv, acc[r][1] * inv,
                               acc[r][2] * inv, acc[r][3] * inv);
        *reinterpret_cast<float4*>(&g_G[b][c0 + ty * 8 + r][tx * 4]) = v;
    }
}

// fused axon MLP + attention update + histories + next-step a_mean.
// block = 64 c rows, 256 threads. dyn smem: Gt[64*128] + BUF(33792 floats).
// BUF phase1: w1 transposed [k=128][h=256] stride 260 (16B-aligned padding).
// BUF phase2: Hs[64][256] at 0, w2 transposed [h=256][j=64] stride 68 at 16384.
#define W1T_STRIDE 260
#define W2T_STRIDE 68
#define BUF_FLOATS 33792
#define MLP_SMEM ((64 * 128 + BUF_FLOATS) * 4)

extern __shared__ float dsm[];

__global__ void __launch_bounds__(256) k_mlp_update(
        int t, const int* __restrict__ prog_op,
        const float* __restrict__ w1, const float* __restrict__ b1,
        const float* __restrict__ w2, const float* __restrict__ b2,
        const float* __restrict__ ins_hist,
        float* __restrict__ att_hist,
        float* __restrict__ trans_hist) {
    float* Gt = dsm;               // [64][128]
    float* BUF = dsm + 64 * 128;
    int b = blockIdx.y, c0 = blockIdx.x * 64;
    int tid = threadIdx.x;

    // load gathered tile (coalesced)
#pragma unroll 4
    for (int k = 0; k < 32; k++) {
        int lin = k * 256 + tid;
        int r = lin >> 7, e = lin & 127;
        Gt[r * 128 + e] = g_G[b][c0 + r][e];
    }
    // stage w1 transposed: BUF[k*260 + h] = w1[h*128 + k] (coalesced reads)
    for (int m = 0; m < 128; m++) {
        int lin = m * 256 + tid;
        int h = lin >> 7, k = lin & 127;
        BUF[k * W1T_STRIDE + h] = w1[lin];
    }
    __syncthreads();

    // phase 1: hidden[64][256] = Gt @ w1T ; tile: 8 rows x 8 h per thread
    int tx = tid & 31, ty = tid >> 5;
    float acc[8][8];
#pragma unroll
    for (int i = 0; i < 8; i++) {
        float bb = b1[tx * 8 + i];
#pragma unroll
        for (int r = 0; r < 8; r++) acc[r][i] = bb;
    }
#pragma unroll 2
    for (int k = 0; k < 128; k++) {
        float4 w0 = *reinterpret_cast<const float4*>(&BUF[k * W1T_STRIDE + tx * 8]);
        float4 w1v = *reinterpret_cast<const float4*>(&BUF[k * W1T_STRIDE + tx * 8 + 4]);
#pragma unroll
        for (int r = 0; r < 8; r++) {
            float g = Gt[(ty * 8 + r) * 128 + k];
            acc[r][0] += g * w0.x;  acc[r][1] += g * w0.y;
            acc[r][2] += g * w0.z;  acc[r][3] += g * w0.w;
            acc[r][4] += g * w1v.x; acc[r][5] += g * w1v.y;
            acc[r][6] += g * w1v.z; acc[r][7] += g * w1v.w;
        }
    }
    __syncthreads();
    // write Hs = relu(acc) into BUF[0..16383], stage w2T at BUF+16384
#pragma unroll
    for (int r = 0; r < 8; r++) {
        float4 h0 = make_float4(fmaxf(acc[r][0], 0.f), fmaxf(acc[r][1], 0.f),
                                fmaxf(acc[r][2], 0.f), fmaxf(acc[r][3], 0.f));
        float4 h1 = make_float4(fmaxf(acc[r][4], 0.f), fmaxf(acc[r][5], 0.f),
                                fmaxf(acc[r][6], 0.f), fmaxf(acc[r][7], 0.f));
        *reinterpret_cast<float4*>(&BUF[(ty * 8 + r) * 256 + tx * 8]) = h0;
        *reinterpret_cast<float4*>(&BUF[(ty * 8 + r) * 256 + tx * 8 + 4]) = h1;
    }
    float* w2T = BUF + 16384;
    for (int m = 0; m < 64; m++) {
        int lin = m * 256 + tid;
        int j = lin >> 8, h = lin & 255;
        w2T[h * W2T_STRIDE + j] = w2[lin];
    }
    __syncthreads();

    // phase 2: trans[64][64] = Hs @ w2T ; tile: 4 rows x 4 j per thread
    int tx2 = tid & 15, ty2 = tid >> 4;
    float a2[4][4];
#pragma unroll
    for (int i = 0; i < 4; i++) {
        float bb = b2[tx2 * 4 + i];
#pragma unroll
        for (int r = 0; r < 4; r++) a2[r][i] = bb;
    }
#pragma unroll 2
    for (int h = 0; h < 256; h++) {
        float4 wv = *reinterpret_cast<const float4*>(&w2T[h * W2T_STRIDE + tx2 * 4]);
#pragma unroll
        for (int r = 0; r < 4; r++) {
            float hv = BUF[(ty2 * 4 + r) * 256 + h];
            a2[r][0] += hv * wv.x; a2[r][1] += hv * wv.y;
            a2[r][2] += hv * wv.z; a2[r][3] += hv * wv.w;
        }
    }

    // epilogue: skip + gated update + leaky clip + histories + a_mean
    int op = prog_op[b * TT + t];
    float insg = (op == 1) ? 1.f : 0.f;
    float trg  = (op == 2) ? 1.f : 0.f;
    float rsum[4];
#pragma unroll
    for (int r = 0; r < 4; r++) {
        int cl = ty2 * 4 + r;
        int c = c0 + cl;
        float4 tr;
        tr.x = a2[r][0] + Gt[cl * 128 + IDD + tx2 * 4 + 0];
        tr.y = a2[r][1] + Gt[cl * 128 + IDD + tx2 * 4 + 1];
        tr.z = a2[r][2] + Gt[cl * 128 + IDD + tx2 * 4 + 2];
        tr.w = a2[r][3] + Gt[cl * 128 + IDD + tx2 * 4 + 3];
        size_t hbase = (((size_t)t * BQ + b) * CC + c) * AD + tx2 * 4;
        float4 iv = *reinterpret_cast<const float4*>(&ins_hist[hbase]);
        float4 av = *reinterpret_cast<const float4*>(&g_att[b][c][tx2 * 4]);
        float4 nv;
        nv.x = av.x + insg * iv.x + trg * tr.x;
        nv.y = av.y + insg * iv.y + trg * tr.y;
        nv.z = av.z + insg * iv.z + trg * tr.z;
        nv.w = av.w + insg * iv.w + trg * tr.w;
        nv.x = fminf(fmaxf((nv.x >= 0.f) ? nv.x : 0.01f * nv.x, -1.f), 2.f);
        nv.y = fminf(fmaxf((nv.y >= 0.f) ? nv.y : 0.01f * nv.y, -1.f), 2.f);
        nv.z = fminf(fmaxf((nv.z >= 0.f) ? nv.z : 0.01f * nv.z, -1.f), 2.f);
        nv.w = fminf(fmaxf((nv.w >= 0.f) ? nv.w : 0.01f * nv.w, -1.f), 2.f);
        *reinterpret_cast<float4*>(&g_att[b][c][tx2 * 4]) = nv;
        *reinterpret_cast<float4*>(&att_hist[hbase]) = nv;
        *reinterpret_cast<float4*>(&trans_hist[hbase]) = tr;
        rsum[r] = nv.x + nv.y + nv.z + nv.w;
    }
#pragma unroll
    for (int o = 1; o < 16; o <<= 1) {
#pragma unroll
        for (int r = 0; r < 4; r++)
            rsum[r] += __shfl_xor_sync(0xffffffffu, rsum[r], o);
    }
    if (tx2 == 0) {
#pragma unroll
        for (int r = 0; r < 4; r++)
            g_amean[b][c0 + ty2 * 4 + r] = rsum[r] * (1.f / AD);
    }
}

// log_softmax over C of final a_mean; one block per batch
__global__ void k_softmax(float* __restrict__ out) {
    __shared__ float red[256];
    int b = blockIdx.x, tid = threadIdx.x;
    float mx = -1e30f;
    for (int c = tid; c < CC; c += 256) mx = fmaxf(mx, g_amean[b][c]);
    red[tid] = mx;
    __syncthreads();
    for (int s = 128; s > 0; s >>= 1) {
        if (tid < s) red[tid] = fmaxf(red[tid], red[tid + s]);
        __syncthreads();
    }
    mx = red[0];
    __syncthreads();
    float sum = 0.f;
    for (int c = tid; c < CC; c += 256) sum += expf(g_amean[b][c] - mx);
    red[tid] = sum;
    __syncthreads();
    for (int s = 128; s > 0; s >>= 1) {
        if (tid < s) red[tid] += red[tid + s];
        __syncthreads();
    }
    float lse = mx + logf(red[0]);
    for (int c = tid; c < CC; c += 256) out[(size_t)b * CC + c] = g_amean[b][c] - lse;
}

// ---------------- launch ------------------------------------------------------
extern "C" void kernel_launch(void* const* d_in, const int* in_sizes, int n_in,
                              void* d_out, int out_size) {
    const int*   scene    = (const int*)d_in[0];
    const int*   prog_op  = (const int*)d_in[1];
    const int*   prog_arg = (const int*)d_in[2];
    const float* attr_in  = (const float*)d_in[3];
    const float* attr_out = (const float*)d_in[4];
    const float* attr_id  = (const float*)d_in[5];
    const float* conc_in  = (const float*)d_in[6];
    const float* conc_out = (const float*)d_in[7];
    const float* conc_id  = (const float*)d_in[8];
    const float* att_init = (const float*)d_in[11];
    const float* axon_w1  = (const float*)d_in[12];
    const float* axon_b1  = (const float*)d_in[13];
    const float* axon_w2  = (const float*)d_in[14];
    const float* axon_b2  = (const float*)d_in[15];
    const float* meta_w1  = (const float*)d_in[16];
    const float* meta_b1  = (const float*)d_in[17];
    const float* meta_w2  = (const float*)d_in[18];
    const float* meta_b2  = (const float*)d_in[19];

    float* out        = (float*)d_out;
    float* att_hist   = out + (size_t)BQ * CC;
    float* ins_hist   = att_hist + (size_t)TT * BQ * CC * AD;
    float* trans_hist = ins_hist + (size_t)TT * BQ * CC * AD;

    // Unconditional (no static guards — harness rule). Idempotent, not a
    // stream op, legal during graph capture.
    cudaFuncSetAttribute(k_mlp_update,
                         cudaFuncAttributeMaxDynamicSharedMemorySize, MLP_SMEM);

    k_objects<<<BQ * NOBJ, 128>>>(scene, attr_in, attr_out, attr_id);
    k_args<<<TT * BQ, 128>>>(prog_arg, conc_out);
    k_att_init<<<(BQ * CC * AD + 255) / 256, 256>>>(att_init);
    k_amean_init<<<(BQ * CC + 255) / 256, 256>>>(att_init);
    k_meta<<<BQ, 256>>>(prog_op, meta_w1, meta_b1, meta_w2, meta_b2, att_init);
    k_proj_ins<<<dim3(CC / 16, BQ, TT), 256>>>(conc_out, ins_hist);

    for (int t = 0; t < TT; t++) {
        k_M<<<dim3(NCHUNK, BQ), 256>>>(conc_out, conc_id);
        k_Mred<<<(BQ * ED * ED) / 256, 256>>>();
        k_G<<<dim3(CC / 64, BQ), 256>>>(conc_in);
        k_mlp_update<<<dim3(CC / 64, BQ), 256, MLP_SMEM>>>(
            t, prog_op, axon_w1, axon_b1, axon_w2, axon_b2,
            ins_hist, att_hist, trans_hist);
    }
    k_softmax<<<BQ, 256>>>(out);
}

// round 4
// speedup vs baseline: 8.4309x; 1.0443x over previous
#include <cuda_runtime.h>
#include <math.h>
#include <stdint.h>

// Problem dims
#define BQ 8
#define NOBJ 128
#define NATT 4
#define TT 12
#define MC 2048
#define ED 128
#define IDD 64
#define AD 64
#define HD 256
#define CC (MC + NOBJ)   // 2176
#define NCHUNK 17        // CC / 128

// ---------------- scratch (device globals; no allocs allowed) ----------------
__device__ float g_obj_in [BQ][NOBJ][ED];
__device__ float g_obj_out[BQ][NOBJ][ED];
__device__ float g_obj_id [BQ][NOBJ][IDD];
__device__ float g_att   [BQ][CC][AD];     // current attention state
__device__ float g_amean [BQ][CC];         // mean over AD of g_att
__device__ float g_meta  [TT][BQ][AD];     // meta after update at step t
__device__ float g_arg   [TT][BQ][ED];     // gathered arguments
__device__ float g_Mpart [BQ][NCHUNK][ED*ED];
__device__ float g_M     [BQ][ED*ED];      // [e][d]
__device__ float g_w1T   [ED][HD];         // axon w1 transposed [k][h]
__device__ float g_w2T   [HD][AD];         // axon w2 transposed [h][j]

// ---------------- row accessors (concept part shared across batch) ----------
__device__ __forceinline__ const float* axon_row(const float* conc_out, int b, int c) {
    return (c < MC) ? (conc_out + (size_t)c * ED) : &g_obj_out[b][c - MC][0];
}
__device__ __forceinline__ const float* dend_row(const float* conc_in, int b, int c) {
    return (c < MC) ? (conc_in + (size_t)c * ED) : &g_obj_in[b][c - MC][0];
}
__device__ __forceinline__ const float* id_row(const float* conc_id, int b, int c) {
    return (c < MC) ? (conc_id + (size_t)c * IDD) : &g_obj_id[b][c - MC][0];
}

// ---------------- init kernels ----------------------------------------------
// one block per (b, n); thread d sums the 4 attribute embeddings
__global__ void k_objects(const int* __restrict__ scene,
                          const float* __restrict__ a_in,
                          const float* __restrict__ a_out,
                          const float* __restrict__ a_id) {
    int bn = blockIdx.x;
    int b = bn / NOBJ, n = bn % NOBJ;
    int d = threadIdx.x;
    const int* sc = scene + (b * NOBJ + n) * NATT;
    float si = 0.f, so = 0.f, sid = 0.f;
#pragma unroll
    for (int a = 0; a < NATT; a++) {
        int s = sc[a];
        float m = (s != -1) ? 1.f : 0.f;
        int idx = s + 1;
        si += m * a_in[(size_t)idx * ED + d];
        so += m * a_out[(size_t)idx * ED + d];
        if (d < IDD) sid += m * a_id[(size_t)idx * IDD + d];
    }
    g_obj_in[b][n][d] = si;
    g_obj_out[b][n][d] = so;
    if (d < IDD) g_obj_id[b][n][d] = sid;
}

// g_arg[t][b] = concept_emb_out[program_arg[b][t]]
__global__ void k_args(const int* __restrict__ prog_arg,
                       const float* __restrict__ conc_out) {
    int tb = blockIdx.x;
    int t = tb / BQ, b = tb % BQ;
    int arg = prog_arg[b * TT + t];
    g_arg[t][b][threadIdx.x] = conc_out[(size_t)arg * ED + threadIdx.x];
}

// pre-transpose axon weights once: coalesced reads, scattered writes (one-time)
__global__ void k_prep(const float* __restrict__ w1, const float* __restrict__ w2) {
    int i = blockIdx.x * blockDim.x + threadIdx.x;
    if (i < HD * ED) {
        int h = i >> 7, k = i & 127;          // w1 is [HD][ED]
        g_w1T[k][h] = w1[i];
    }
    if (i < AD * HD) {
        int j = i >> 8, h = i & 255;          // w2 is [AD][HD]
        g_w2T[h][j] = w2[i];
    }
}

// attention state init + initial a_mean, one kernel
__global__ void k_init(const float* __restrict__ att_init) {
    int i = blockIdx.x * blockDim.x + threadIdx.x;
    if (i < BQ * CC * AD)
        ((float*)g_att)[i] = att_init[i & (AD - 1)];
    if (i < BQ * CC) {
        float s = 0.f;
#pragma unroll
        for (int a = 0; a < AD; a++) s += att_init[a];
        ((float*)g_amean)[i] = s * (1.f / AD);
    }
}

// meta recurrence: warp-cooperative dots, coalesced weight reads.
__global__ void k_meta(const int* __restrict__ prog_op,
                       const float* __restrict__ w1, const float* __restrict__ b1,
                       const float* __restrict__ w2, const float* __restrict__ b2,
                       const float* __restrict__ att_init) {
    __shared__ float x[AD + ED];   // meta(64) || arg(128)
    __shared__ float hid[HD];
    __shared__ float nm[AD];
    int b = blockIdx.x, tid = threadIdx.x;
    int warp = tid >> 5, lane = tid & 31;
    if (tid < AD) x[tid] = att_init[tid];
    for (int t = 0; t < TT; t++) {
        if (tid < ED) x[AD + tid] = g_arg[t][b][tid];
        __syncthreads();
        for (int hh = 0; hh < 32; hh++) {
            int h = warp * 32 + hh;
            const float* wr = w1 + (size_t)h * (AD + ED);
            float p = 0.f;
#pragma unroll
            for (int m = 0; m < 6; m++) p += x[lane + 32 * m] * wr[lane + 32 * m];
#pragma unroll
            for (int o = 16; o; o >>= 1) p += __shfl_xor_sync(0xffffffffu, p, o);
            if (lane == 0) hid[h] = fmaxf(p + b1[h], 0.f);
        }
        __syncthreads();
        float mg = (prog_op[b * TT + t] == 0) ? 1.f : 0.f;
        for (int jj = 0; jj < 8; jj++) {
            int j = warp * 8 + jj;
            const float* wr = w2 + (size_t)j * HD;
            float p = 0.f;
#pragma unroll
            for (int m = 0; m < 8; m++) p += hid[lane + 32 * m] * wr[lane + 32 * m];
#pragma unroll
            for (int o = 16; o; o >>= 1) p += __shfl_xor_sync(0xffffffffu, p, o);
            if (lane == 0) nm[j] = mg * (p + b2[j]) + (1.f - mg) * x[j];
        }
        __syncthreads();
        if (tid < AD) {
            x[tid] = nm[tid];
            g_meta[t][b][tid] = nm[tid];
        }
        __syncthreads();
    }
}

// proj + ins_hist: warp-cooperative dots
__global__ void k_proj_ins(const float* __restrict__ conc_out,
                           float* __restrict__ ins_hist) {
    __shared__ float arg_s[ED];
    __shared__ float meta_s[AD];
    __shared__ float proj_s[16];
    int t = blockIdx.z, b = blockIdx.y, c0 = blockIdx.x * 16;
    int tid = threadIdx.x;
    if (tid < ED) arg_s[tid] = g_arg[t][b][tid];
    else if (tid < ED + AD) meta_s[tid - ED] = g_meta[t][b][tid - ED];
    __syncthreads();
    int warp = tid >> 5, lane = tid & 31;
#pragma unroll
    for (int r = 0; r < 2; r++) {
        int cl = warp * 2 + r;
        const float* ax = axon_row(conc_out, b, c0 + cl);
        float p = 0.f;
#pragma unroll
        for (int m = 0; m < 4; m++) p += arg_s[lane + 32 * m] * ax[lane + 32 * m];
#pragma unroll
        for (int o = 16; o; o >>= 1) p += __shfl_xor_sync(0xffffffffu, p, o);
        if (lane == 0) proj_s[cl] = p * (1.f / ED);
    }
    __syncthreads();
    float* outp = ins_hist + (((size_t)t * BQ + b) * CC + c0) * AD;
#pragma unroll
    for (int k = 0; k < 4; k++) {
        int i = k * 256 + tid;
        outp[i] = proj_s[i >> 6] * meta_s[i & 63];
    }
}

// ---------------- per-step kernels -------------------------------------------
// M partials
__global__ void k_M(const float* __restrict__ conc_out,
                    const float* __restrict__ conc_id) {
    int b = blockIdx.y, ch = blockIdx.x;
    int c0 = ch * 128;
    int tid = threadIdx.x;
    int ty = tid >> 4, tx = tid & 15;
    __shared__ __align__(16) float sax[8][ED];
    __shared__ __align__(16) float sia[8][ED];
    float acc[8][8];
#pragma unroll
    for (int i = 0; i < 8; i++)
#pragma unroll
        for (int j = 0; j < 8; j++) acc[i][j] = 0.f;

    for (int g = 0; g < 16; g++) {
        int cb = c0 + g * 8;
        if (tid < 128) {
#pragma unroll
            for (int r = 0; r < 8; r++) {
                int c = cb + r;
                sax[r][tid] = axon_row(conc_out, b, c)[tid] * g_amean[b][c];
            }
        } else {
            int d = tid - 128;
#pragma unroll
            for (int r = 0; r < 8; r++) {
                int c = cb + r;
                sia[r][d] = (d < IDD) ? id_row(conc_id, b, c)[d]
                                      : g_att[b][c][d - IDD];
            }
        }
        __syncthreads();
#pragma unroll
        for (int r = 0; r < 8; r++) {
            float4 a0 = *reinterpret_cast<const float4*>(&sax[r][ty * 8]);
            float4 a1 = *reinterpret_cast<const float4*>(&sax[r][ty * 8 + 4]);
            float4 b0 = *reinterpret_cast<const float4*>(&sia[r][tx * 8]);
            float4 b1 = *reinterpret_cast<const float4*>(&sia[r][tx * 8 + 4]);
            float av[8] = {a0.x, a0.y, a0.z, a0.w, a1.x, a1.y, a1.z, a1.w};
            float bv[8] = {b0.x, b0.y, b0.z, b0.w, b1.x, b1.y, b1.z, b1.w};
#pragma unroll
            for (int i = 0; i < 8; i++)
#pragma unroll
                for (int j = 0; j < 8; j++) acc[i][j] += av[i] * bv[j];
        }
        __syncthreads();
    }
    float* outp = g_Mpart[b][ch];
#pragma unroll
    for (int i = 0; i < 8; i++)
#pragma unroll
        for (int j = 0; j < 8; j++)
            outp[(ty * 8 + i) * ED + tx * 8 + j] = acc[i][j];
}

// deterministic reduce of the 17 chunk partials
__global__ void k_Mred() {
    int i = blockIdx.x * blockDim.x + threadIdx.x;
    int b = i >> 14;
    int ed = i & 16383;
    float s = 0.f;
#pragma unroll
    for (int k = 0; k < NCHUNK; k++) s += g_Mpart[b][k][ed];
    g_M[b][ed] = s;
}

// =============================================================================
// Fused G + MLP + update kernel.
// Block = 64 c rows, 256 threads, 2 blocks/SM.
// smem: Gt[64][128] persistent (32KB) + POOL (80KB):
//   Phase A: den[64][128] @0, Mchunk[32][128] @8192
//   Phase B: w1 chunk [32][256] @0
//   Phase C: Hs[64][256] @0, w2 chunk [64][64] @16384
// =============================================================================
#define GMLP_SMEM ((8192 + 20480) * 4)   // 114688 B

extern __shared__ float dsm[];

__global__ void __launch_bounds__(256, 2) k_gmlp(
        int t, const int* __restrict__ prog_op,
        const float* __restrict__ conc_in,
        const float* __restrict__ b1, const float* __restrict__ b2,
        const float* __restrict__ ins_hist,
        float* __restrict__ att_hist,
        float* __restrict__ trans_hist) {
    float* Gt = dsm;                 // [64][128]
    float* POOL = dsm + 8192;
    int b = blockIdx.y, c0 = blockIdx.x * 64;
    int tid = threadIdx.x;
    int tx = tid & 31, ty = tid >> 5;

    // ---------- Phase A: G tile = dendron @ M / CC ----------
    {
        float* den = POOL;           // [64][128]
        float* Ms = POOL + 8192;     // [32][128]
#pragma unroll 4
        for (int k = 0; k < 32; k++) {
            int lin = k * 256 + tid;
            int r = lin >> 7, e = lin & 127;
            den[r * 128 + e] = dend_row(conc_in, b, c0 + r)[e];
        }
        float acc[8][4];
#pragma unroll
        for (int r = 0; r < 8; r++)
#pragma unroll
            for (int i = 0; i < 4; i++) acc[r][i] = 0.f;
        const float* Mb = g_M[b];
        for (int e0 = 0; e0 < 128; e0 += 32) {
            __syncthreads();
#pragma unroll 4
            for (int k = 0; k < 16; k++) {
                int lin = k * 256 + tid;
                int er = lin >> 7, d = lin & 127;
                Ms[er * 128 + d] = Mb[(e0 + er) * 128 + d];
            }
            __syncthreads();
#pragma unroll 2
            for (int e = 0; e < 32; e++) {
                float4 mv = *reinterpret_cast<const float4*>(&Ms[e * 128 + tx * 4]);
#pragma unroll
                for (int r = 0; r < 8; r++) {
                    float dv = den[(ty * 8 + r) * 128 + e0 + e];
                    acc[r][0] += dv * mv.x;
                    acc[r][1] += dv * mv.y;
                    acc[r][2] += dv * mv.z;
                    acc[r][3] += dv * mv.w;
                }
            }
        }
        const float inv = 1.f / CC;
#pragma unroll
        for (int r = 0; r < 8; r++) {
            float4 v = make_float4(acc[r][0] * inv, acc[r][1] * inv,
                                   acc[r][2] * inv, acc[r][3] * inv);
            *reinterpret_cast<float4*>(&Gt[(ty * 8 + r) * 128 + tx * 4]) = v;
        }
    }
    __syncthreads();   // den/Ms dead; Gt ready

    // ---------- Phase B: hidden[64][256] = Gt @ w1T, k-chunked ----------
    float acc[8][8];
#pragma unroll
    for (int i = 0; i < 8; i++) {
        float bb = b1[tx * 8 + i];
#pragma unroll
        for (int r = 0; r < 8; r++) acc[r][i] = bb;
    }
    {
        float* w1c = POOL;           // [32][256]
        for (int kc = 0; kc < 4; kc++) {
#pragma unroll 4
            for (int kk = 0; kk < 32; kk++) {
                int lin = kk * 256 + tid;
                int k = lin >> 8, h = lin & 255;
                w1c[k * 256 + h] = g_w1T[kc * 32 + k][h];
            }
            __syncthreads();
#pragma unroll 2
            for (int k = 0; k < 32; k++) {
                float4 w0 = *reinterpret_cast<const float4*>(&w1c[k * 256 + tx * 8]);
                float4 w1v = *reinterpret_cast<const float4*>(&w1c[k * 256 + tx * 8 + 4]);
#pragma unroll
                for (int r = 0; r < 8; r++) {
                    float g = Gt[(ty * 8 + r) * 128 + kc * 32 + k];
                    acc[r][0] += g * w0.x;  acc[r][1] += g * w0.y;
                    acc[r][2] += g * w0.z;  acc[r][3] += g * w0.w;
                    acc[r][4] += g * w1v.x; acc[r][5] += g * w1v.y;
                    acc[r][6] += g * w1v.z; acc[r][7] += g * w1v.w;
                }
            }
            __syncthreads();
        }
    }

    // ---------- Phase C: trans[64][64] = relu(H) @ w2T, h-chunked ----------
    float* Hs = POOL;                // [64][256]
    float* w2c = POOL + 16384;       // [64][64]
#pragma unroll
    for (int r = 0; r < 8; r++) {
        float4 h0 = make_float4(fmaxf(acc[r][0], 0.f), fmaxf(acc[r][1], 0.f),
                                fmaxf(acc[r][2], 0.f), fmaxf(acc[r][3], 0.f));
        float4 h1 = make_float4(fmaxf(acc[r][4], 0.f), fmaxf(acc[r][5], 0.f),
                                fmaxf(acc[r][6], 0.f), fmaxf(acc[r][7], 0.f));
        *reinterpret_cast<float4*>(&Hs[(ty * 8 + r) * 256 + tx * 8]) = h0;
        *reinterpret_cast<float4*>(&Hs[(ty * 8 + r) * 256 + tx * 8 + 4]) = h1;
    }
    int tx2 = tid & 15, ty2 = tid >> 4;
    float a2[4][4];
#pragma unroll
    for (int i = 0; i < 4; i++) {
        float bb = b2[tx2 * 4 + i];
#pragma unroll
        for (int r = 0; r < 4; r++) a2[r][i] = bb;
    }
    for (int hc = 0; hc < 4; hc++) {
        __syncthreads();
#pragma unroll 4
        for (int kk = 0; kk < 16; kk++) {
            int lin = kk * 256 + tid;
            int h = lin >> 6, j = lin & 63;
            w2c[h * 64 + j] = g_w2T[hc * 64 + h][j];
        }
        __syncthreads();
#pragma unroll 2
        for (int h = 0; h < 64; h++) {
            float4 wv = *reinterpret_cast<const float4*>(&w2c[h * 64 + tx2 * 4]);
#pragma unroll
            for (int r = 0; r < 4; r++) {
                float hv = Hs[(ty2 * 4 + r) * 256 + hc * 64 + h];
                a2[r][0] += hv * wv.x; a2[r][1] += hv * wv.y;
                a2[r][2] += hv * wv.z; a2[r][3] += hv * wv.w;
            }
        }
    }

    // ---------- Epilogue: skip + gated update + clip + histories + a_mean ----
    int op = prog_op[b * TT + t];
    float insg = (op == 1) ? 1.f : 0.f;
    float trg  = (op == 2) ? 1.f : 0.f;
    float rsum[4];
#pragma unroll
    for (int r = 0; r < 4; r++) {
        int cl = ty2 * 4 + r;
        int c = c0 + cl;
        float4 tr;
        tr.x = a2[r][0] + Gt[cl * 128 + IDD + tx2 * 4 + 0];
        tr.y = a2[r][1] + Gt[cl * 128 + IDD + tx2 * 4 + 1];
        tr.z = a2[r][2] + Gt[cl * 128 + IDD + tx2 * 4 + 2];
        tr.w = a2[r][3] + Gt[cl * 128 + IDD + tx2 * 4 + 3];
        size_t hbase = (((size_t)t * BQ + b) * CC + c) * AD + tx2 * 4;
        float4 iv = *reinterpret_cast<const float4*>(&ins_hist[hbase]);
        float4 av = *reinterpret_cast<const float4*>(&g_att[b][c][tx2 * 4]);
        float4 nv;
        nv.x = av.x + insg * iv.x + trg * tr.x;
        nv.y = av.y + insg * iv.y + trg * tr.y;
        nv.z = av.z + insg * iv.z + trg * tr.z;
        nv.w = av.w + insg * iv.w + trg * tr.w;
        nv.x = fminf(fmaxf((nv.x >= 0.f) ? nv.x : 0.01f * nv.x, -1.f), 2.f);
        nv.y = fminf(fmaxf((nv.y >= 0.f) ? nv.y : 0.01f * nv.y, -1.f), 2.f);
        nv.z = fminf(fmaxf((nv.z >= 0.f) ? nv.z : 0.01f * nv.z, -1.f), 2.f);
        nv.w = fminf(fmaxf((nv.w >= 0.f) ? nv.w : 0.01f * nv.w, -1.f), 2.f);
        *reinterpret_cast<float4*>(&g_att[b][c][tx2 * 4]) = nv;
        *reinterpret_cast<float4*>(&att_hist[hbase]) = nv;
        *reinterpret_cast<float4*>(&trans_hist[hbase]) = tr;
        rsum[r] = nv.x + nv.y + nv.z + nv.w;
    }
#pragma unroll
    for (int o = 1; o < 16; o <<= 1) {
#pragma unroll
        for (int r = 0; r < 4; r++)
            rsum[r] += __shfl_xor_sync(0xffffffffu, rsum[r], o);
    }
    if (tx2 == 0) {
#pragma unroll
        for (int r = 0; r < 4; r++)
            g_amean[b][c0 + ty2 * 4 + r] = rsum[r] * (1.f / AD);
    }
}

// log_softmax over C of final a_mean; one block per batch
__global__ void k_softmax(float* __restrict__ out) {
    __shared__ float red[256];
    int b = blockIdx.x, tid = threadIdx.x;
    float mx = -1e30f;
    for (int c = tid; c < CC; c += 256) mx = fmaxf(mx, g_amean[b][c]);
    red[tid] = mx;
    __syncthreads();
    for (int s = 128; s > 0; s >>= 1) {
        if (tid < s) red[tid] = fmaxf(red[tid], red[tid + s]);
        __syncthreads();
    }
    mx = red[0];
    __syncthreads();
    float sum = 0.f;
    for (int c = tid; c < CC; c += 256) sum += expf(g_amean[b][c] - mx);
    red[tid] = sum;
    __syncthreads();
    for (int s = 128; s > 0; s >>= 1) {
        if (tid < s) red[tid] += red[tid + s];
        __syncthreads();
    }
    float lse = mx + logf(red[0]);
    for (int c = tid; c < CC; c += 256) out[(size_t)b * CC + c] = g_amean[b][c] - lse;
}

// ---------------- launch ------------------------------------------------------
extern "C" void kernel_launch(void* const* d_in, const int* in_sizes, int n_in,
                              void* d_out, int out_size) {
    const int*   scene    = (const int*)d_in[0];
    const int*   prog_op  = (const int*)d_in[1];
    const int*   prog_arg = (const int*)d_in[2];
    const float* attr_in  = (const float*)d_in[3];
    const float* attr_out = (const float*)d_in[4];
    const float* attr_id  = (const float*)d_in[5];
    const float* conc_in  = (const float*)d_in[6];
    const float* conc_out = (const float*)d_in[7];
    const float* conc_id  = (const float*)d_in[8];
    const float* att_init = (const float*)d_in[11];
    const float* axon_w1  = (const float*)d_in[12];
    const float* axon_b1  = (const float*)d_in[13];
    const float* axon_w2  = (const float*)d_in[14];
    const float* axon_b2  = (const float*)d_in[15];
    const float* meta_w1  = (const float*)d_in[16];
    const float* meta_b1  = (const float*)d_in[17];
    const float* meta_w2  = (const float*)d_in[18];
    const float* meta_b2  = (const float*)d_in[19];

    float* out        = (float*)d_out;
    float* att_hist   = out + (size_t)BQ * CC;
    float* ins_hist   = att_hist + (size_t)TT * BQ * CC * AD;
    float* trans_hist = ins_hist + (size_t)TT * BQ * CC * AD;

    cudaFuncSetAttribute(k_gmlp,
                         cudaFuncAttributeMaxDynamicSharedMemorySize, GMLP_SMEM);

    k_objects<<<BQ * NOBJ, 128>>>(scene, attr_in, attr_out, attr_id);
    k_args<<<TT * BQ, 128>>>(prog_arg, conc_out);
    k_prep<<<(HD * ED + 255) / 256, 256>>>(axon_w1, axon_w2);
    k_init<<<(BQ * CC * AD + 255) / 256, 256>>>(att_init);
    k_meta<<<BQ, 256>>>(prog_op, meta_w1, meta_b1, meta_w2, meta_b2, att_init);
    k_proj_ins<<<dim3(CC / 16, BQ, TT), 256>>>(conc_out, ins_hist);

    for (int t = 0; t < TT; t++) {
        k_M<<<dim3(NCHUNK, BQ), 256>>>(conc_out, conc_id);
        k_Mred<<<(BQ * ED * ED) / 256, 256>>>();
        k_gmlp<<<dim3(CC / 64, BQ), 256, GMLP_SMEM>>>(
            t, prog_op, conc_in, axon_b1, axon_b2,
            ins_hist, att_hist, trans_hist);
    }
    k_softmax<<<BQ, 256>>>(out);
}